// round 10
// baseline (speedup 1.0000x reference)
#include <cuda_runtime.h>

// Problem constants
#define NN 2
#define CO 64
#define CI 3
#define HH 256
#define WF 129
#define HW (HH*WF)            // 33024 complex per (n,ci) plane
#define PTS (NN*HH*WF)        // 66048 frequency points
#define NCOLS (NN*CI*WF)      // 774 column FFTs
#define NROWS (NN*CI*HH)      // 1536 row FFTs

// Scratch: Xhat (N, C_in, H, Wf) complex — column-iFFT done in place here.
__device__ float2 g_xhat[NN*CI*HW];

__device__ __forceinline__ float2 cmul(float2 a, float2 b) {
    return make_float2(a.x*b.x - a.y*b.y, a.x*b.y + a.y*b.x);
}

// ---------------------------------------------------------------------------
// Kernel 1: per-frequency solve, reduce over C_out, write Xhat/64.
// One thread per (n,h,w). Coalesced float2 loads along w.
// ---------------------------------------------------------------------------
__global__ void __launch_bounds__(256) solve_kernel(
    const float* __restrict__ X, const float* __restrict__ D,
    const float* __restrict__ Y, const float* __restrict__ alpha)
{
    int idx = blockIdx.x * blockDim.x + threadIdx.x;
    if (idx >= PTS) return;
    int w = idx % WF;
    int h = (idx / WF) % HH;
    int n = idx / (HH*WF);

    const float2* __restrict__ Xp = (const float2*)X;
    const float2* __restrict__ Dp = (const float2*)D;
    const float2* __restrict__ Yp = (const float2*)Y;

    float a = alpha[n] * (1.0f/3.0f);
    float inv_a = 1.0f / a;
    float a2 = a * a;

    size_t hw = (size_t)h * WF + w;

    float2 x0 = Xp[(size_t)(n*CI + 0)*HW + hw];
    float2 x1 = Xp[(size_t)(n*CI + 1)*HW + hw];
    float2 x2 = Xp[(size_t)(n*CI + 2)*HW + hw];
    float2 ax0 = make_float2(a*x0.x, a*x0.y);
    float2 ax1 = make_float2(a*x1.x, a*x1.y);
    float2 ax2 = make_float2(a*x2.x, a*x2.y);

    float2 acc0 = make_float2(0.f,0.f);
    float2 acc1 = make_float2(0.f,0.f);
    float2 acc2 = make_float2(0.f,0.f);

    const float2* dbase = Dp + (size_t)n*CO*CI*HW + hw;
    const float2* ybase = Yp + (size_t)n*CO*HW + hw;

    #pragma unroll 4
    for (int co = 0; co < CO; ++co) {
        float2 y  = ybase[(size_t)co*HW];
        const float2* dq = dbase + (size_t)co*CI*HW;
        float2 d0 = dq[0];
        float2 d1 = dq[HW];
        float2 d2 = dq[2*HW];

        // Z = Y*D + a*X
        float2 z0 = cmul(y, d0); z0.x += ax0.x; z0.y += ax0.y;
        float2 z1 = cmul(y, d1); z1.x += ax1.x; z1.y += ax1.y;
        float2 z2 = cmul(y, d2); z2.x += ax2.x; z2.y += ax2.y;

        // numerator = sum_ci conj(d)*z  (complex)
        float nr = d0.x*z0.x + d0.y*z0.y
                 + d1.x*z1.x + d1.y*z1.y
                 + d2.x*z2.x + d2.y*z2.y;
        float ni = d0.x*z0.y - d0.y*z0.x
                 + d1.x*z1.y - d1.y*z1.x
                 + d2.x*z2.y - d2.y*z2.x;

        // denominator = a*sum|d|^2 + a^2   (exactly real)
        float ds = d0.x*d0.x + d0.y*d0.y
                 + d1.x*d1.x + d1.y*d1.y
                 + d2.x*d2.x + d2.y*d2.y;
        float invden = 1.0f / (a*ds + a2);
        float fr = nr * invden;
        float fi = ni * invden;

        // acc += z/a - d*f
        acc0.x += z0.x*inv_a - (d0.x*fr - d0.y*fi);
        acc0.y += z0.y*inv_a - (d0.x*fi + d0.y*fr);
        acc1.x += z1.x*inv_a - (d1.x*fr - d1.y*fi);
        acc1.y += z1.y*inv_a - (d1.x*fi + d1.y*fr);
        acc2.x += z2.x*inv_a - (d2.x*fr - d2.y*fi);
        acc2.y += z2.y*inv_a - (d2.x*fi + d2.y*fr);
    }

    const float sc = 1.0f / (float)CO;  // mean over C_out
    g_xhat[(size_t)(n*CI + 0)*HW + hw] = make_float2(acc0.x*sc, acc0.y*sc);
    g_xhat[(size_t)(n*CI + 1)*HW + hw] = make_float2(acc1.x*sc, acc1.y*sc);
    g_xhat[(size_t)(n*CI + 2)*HW + hw] = make_float2(acc2.x*sc, acc2.y*sc);
}

// ---------------------------------------------------------------------------
// 256-point in-place inverse FFT (unnormalized, e^{+i}) in shared memory.
// 128 threads, one butterfly per thread per stage.
// ---------------------------------------------------------------------------
__device__ __forceinline__ void ifft256_shared(float2* s, int tid)
{
    // bit-reversal permutation (8 bits); swap owned by smaller index.
    #pragma unroll
    for (int r = 0; r < 2; ++r) {
        int i = tid + r*128;
        int j = (int)(__brev((unsigned)i) >> 24);
        if (i < j) { float2 t = s[i]; s[i] = s[j]; s[j] = t; }
    }
    __syncthreads();

    #pragma unroll
    for (int len = 2; len <= 256; len <<= 1) {
        int half = len >> 1;
        int k  = tid & (half - 1);
        int i0 = ((tid & ~(half - 1)) << 1) + k;
        int i1 = i0 + half;
        float ang = 6.283185307179586f * (float)k / (float)len;  // +i => inverse
        float sn, cs;
        __sincosf(ang, &sn, &cs);
        float2 w = make_float2(cs, sn);
        float2 u = s[i0];
        float2 v = cmul(s[i1], w);
        s[i0] = make_float2(u.x + v.x, u.y + v.y);
        s[i1] = make_float2(u.x - v.x, u.y - v.y);
        __syncthreads();
    }
}

// ---------------------------------------------------------------------------
// Kernel 2: iFFT along H for every (n,ci,w) column, in place in g_xhat.
// ---------------------------------------------------------------------------
__global__ void __launch_bounds__(128) col_ifft_kernel()
{
    __shared__ float2 s[256];
    int col = blockIdx.x;           // (n*CI+ci)*WF + w
    int nc  = col / WF;
    int w   = col % WF;
    float2* base = g_xhat + (size_t)nc*HW + w;
    int tid = threadIdx.x;

    #pragma unroll
    for (int r = 0; r < 2; ++r) { int h = tid + r*128; s[h] = base[(size_t)h*WF]; }
    __syncthreads();

    ifft256_shared(s, tid);

    #pragma unroll
    for (int r = 0; r < 2; ++r) { int h = tid + r*128; base[(size_t)h*WF] = s[h]; }
}

// ---------------------------------------------------------------------------
// Kernel 3: irfft along W for every (n,ci,h) row: Hermitian-extend 129 -> 256,
// complex iFFT, take real part, apply 1/(256*256) normalization.
// ---------------------------------------------------------------------------
__global__ void __launch_bounds__(128) row_irfft_kernel(float* __restrict__ out)
{
    __shared__ float2 s[256];
    int row = blockIdx.x;           // (n*CI+ci)*HH + h
    const float2* base = g_xhat + (size_t)row * WF;
    int tid = threadIdx.x;

    #pragma unroll
    for (int r = 0; r < 2; ++r) {
        int k = tid + r*128;
        if (k <= 128) {
            s[k] = base[k];
        } else {
            float2 v = base[256 - k];
            s[k] = make_float2(v.x, -v.y);   // conj symmetry
        }
    }
    __syncthreads();

    ifft256_shared(s, tid);

    const float norm = 1.0f / 65536.0f;      // 1/256 per axis
    float* o = out + (size_t)row * 256;
    #pragma unroll
    for (int r = 0; r < 2; ++r) {
        int k = tid + r*128;
        o[k] = s[k].x * norm;
    }
}

// ---------------------------------------------------------------------------
extern "C" void kernel_launch(void* const* d_in, const int* in_sizes, int n_in,
                              void* d_out, int out_size)
{
    const float* X     = (const float*)d_in[0];
    const float* D     = (const float*)d_in[1];
    const float* Y     = (const float*)d_in[2];
    const float* alpha = (const float*)d_in[3];
    // d_in[4] = x_size (int64) — fixed 256x256, hardcoded.
    float* out = (float*)d_out;

    solve_kernel<<<(PTS + 255) / 256, 256>>>(X, D, Y, alpha);
    col_ifft_kernel<<<NCOLS, 128>>>();
    row_irfft_kernel<<<NROWS, 128>>>(out);
}